// round 1
// baseline (speedup 1.0000x reference)
#include <cuda_runtime.h>
#include <math.h>

// Problem constants (from reference): x:(B,256) f32, W1:(4,256), b1:(4),
// weights:(L,4,3), W2:(64,4), b2:(64). out:(B,64) f32.
#define MAX_L   8
#define DIN     256
#define DOUT    64
#define NQ      4
#define ROWS    256     // rows per block
#define THREADS 256
#define TILE    32      // column tile for x staging
#define NT      (DIN / TILE)

// Precomputed Rot(phi,theta,omega) unitaries: per (l,wire) 4 complex = 8 floats.
__device__ float d_rot[MAX_L * NQ * 8];

// ---------------------------------------------------------------------------
// Prelude: compute the L*4 Rot matrices once (they are batch-independent).
// U = Rz(omega) @ Ry(theta) @ Rz(phi):
//   U00 = e^{-i(phi+omega)/2} c     U01 = -e^{+i(phi-omega)/2} s
//   U10 = e^{-i(phi-omega)/2} s     U11 = e^{+i(phi+omega)/2} c
// with c = cos(theta/2), s = sin(theta/2).
// ---------------------------------------------------------------------------
__global__ void rot_precompute_kernel(const float* __restrict__ w, int L) {
    int idx = threadIdx.x;                 // idx = l*4 + wire
    if (idx < L * NQ) {
        float phi = w[idx * 3 + 0];
        float th  = w[idx * 3 + 1];
        float om  = w[idx * 3 + 2];
        float s, c;   sincosf(0.5f * th, &s, &c);
        float sa, ca; sincosf(0.5f * (phi - om), &sa, &ca);   // alpha = (phi-omega)/2
        float sb, cb; sincosf(0.5f * (phi + om), &sb, &cb);   // beta  = (phi+omega)/2
        float* o = d_rot + idx * 8;
        o[0] =  cb * c;  o[1] = -sb * c;    // U00 = e^{-i beta} c
        o[2] = -ca * s;  o[3] = -sa * s;    // U01 = -e^{+i alpha} s
        o[4] =  ca * s;  o[5] = -sa * s;    // U10 = e^{-i alpha} s
        o[6] =  cb * c;  o[7] =  sb * c;    // U11 = e^{+i beta} c
    }
}

__device__ __forceinline__ float2 cmul(float2 a, float2 b) {
    return make_float2(fmaf(a.x, b.x, -a.y * b.y), fmaf(a.x, b.y, a.y * b.x));
}
// acc + u*a (complex fused)
__device__ __forceinline__ float2 cfma(float2 u, float2 a, float2 acc) {
    acc.x = fmaf(u.x, a.x, fmaf(-u.y, a.y, acc.x));
    acc.y = fmaf(u.x, a.y, fmaf( u.y, a.x, acc.y));
    return acc;
}

// ---------------------------------------------------------------------------
// Main fused kernel: one thread = one batch row.
// ---------------------------------------------------------------------------
__global__ void __launch_bounds__(THREADS)
qproj_kernel(const float* __restrict__ x,  const float* __restrict__ W1,
             const float* __restrict__ b1, const float* __restrict__ W2,
             const float* __restrict__ b2, float* __restrict__ out,
             int B, int L)
{
    // x staging tile: 256 rows x 8 float4 (+1 float4 pad -> stride 9 -> no bank conflicts)
    __shared__ float4 xs4[ROWS][TILE / 4 + 1];            // 36.0 KB
    __shared__ float4 w1s[DIN];                           // w1s[c] = W1[0..3][c]  (4 KB)
    __shared__ float  w2t[NQ][DOUT];                      // transposed W2         (1 KB)
    __shared__ float4 b2s4[DOUT / 4];
    __shared__ float4 rots4[MAX_L * NQ * 2];              // 2 float4 per gate
    __shared__ float  b1s[NQ];
    __shared__ float4 zs[ROWS];                           // per-row <Z> (4 KB)

    const int  tid     = threadIdx.x;
    const long rowBase = (long)blockIdx.x * ROWS;

    // ---- stage small weights ----
    for (int c = tid; c < DIN; c += THREADS)
        w1s[c] = make_float4(W1[c], W1[DIN + c], W1[2 * DIN + c], W1[3 * DIN + c]);
    if (tid < DOUT) {
        #pragma unroll
        for (int i = 0; i < NQ; ++i) w2t[i][tid] = W2[tid * NQ + i];
    }
    if (tid < DOUT / 4) b2s4[tid] = reinterpret_cast<const float4*>(b2)[tid];
    if (tid < NQ)       b1s[tid]  = b1[tid];
    for (int i = tid; i < L * NQ * 2; i += THREADS)
        rots4[i] = reinterpret_cast<const float4*>(d_rot)[i];

    // ---- f = x @ W1^T, tiled through shared ----
    float acc0 = 0.f, acc1 = 0.f, acc2 = 0.f, acc3 = 0.f;
    for (int t = 0; t < NT; ++t) {
        __syncthreads();
        // coalesced load: 2048 float4 per tile, 8 per thread
        #pragma unroll
        for (int k = 0; k < (ROWS * TILE / 4) / THREADS; ++k) {
            int q  = tid + k * THREADS;
            int r  = q >> 3;            // TILE/4 = 8 float4 per row
            int c4 = q & 7;
            long rr = rowBase + r;
            if (rr >= B) rr = (long)B - 1;   // safe clamp (B % 256 == 0 in bench)
            xs4[r][c4] = *reinterpret_cast<const float4*>(
                x + rr * DIN + (long)t * TILE + c4 * 4);
        }
        __syncthreads();
        #pragma unroll
        for (int c4 = 0; c4 < TILE / 4; ++c4) {
            float4 xv = xs4[tid][c4];
            #pragma unroll
            for (int e = 0; e < 4; ++e) {
                float  xe = (e == 0) ? xv.x : (e == 1) ? xv.y : (e == 2) ? xv.z : xv.w;
                float4 w  = w1s[t * TILE + c4 * 4 + e];
                acc0 = fmaf(xe, w.x, acc0);
                acc1 = fmaf(xe, w.y, acc1);
                acc2 = fmaf(xe, w.z, acc2);
                acc3 = fmaf(xe, w.w, acc3);
            }
        }
    }

    // ---- per-qubit amplitudes after H, RY(atan f), RZ(atan f^2) ----
    // theta = atan(t): sin(theta) = t / sqrt(1+t^2)
    //   (c - s)/sqrt2 = sqrt((1 - sin th)/2),  (c + s)/sqrt2 = sqrt((1 + sin th)/2)
    // phi = atan(t^2): cos(phi) = 1/sqrt(1+t^4)
    //   cos(phi/2) = sqrt((1+cos phi)/2), sin(phi/2) = sqrt((1-cos phi)/2)  (phi >= 0)
    const float PI_F = 3.14159265358979323846f;
    float fv[NQ];
    fv[0] = tanhf(acc0 + b1s[0]) * PI_F;
    fv[1] = tanhf(acc1 + b1s[1]) * PI_F;
    fv[2] = tanhf(acc2 + b1s[2]) * PI_F;
    fv[3] = tanhf(acc3 + b1s[3]) * PI_F;

    float2 ga[NQ], gb[NQ];   // amplitude of |0>, |1> per qubit
    #pragma unroll
    for (int i = 0; i < NQ; ++i) {
        float t  = fv[i];
        float t2 = t * t;
        float r  = rsqrtf(1.f + t2);
        float st = t * r;                           // sin(theta)
        float u  = sqrtf(fmaxf(0.5f * (1.f - st), 0.f));
        float v  = sqrtf(fmaxf(0.5f * (1.f + st), 0.f));
        float t4 = t2 * t2;
        float r2 = rsqrtf(1.f + t4);                // cos(phi)
        float cp = sqrtf(fmaxf(0.5f * (1.f + r2), 0.f));
        float sp = sqrtf(fmaxf(0.5f * (1.f - r2), 0.f));
        ga[i] = make_float2(u * cp, -u * sp);       // u * e^{-i phi/2}
        gb[i] = make_float2(v * cp,  v * sp);       // v * e^{+i phi/2}
    }

    // ---- product state: amp index bits [q0 q1 q2 q3], wire w -> bit (3-w) ----
    float2 amp[16];
    {
        float2 p01[4], p23[4];
        #pragma unroll
        for (int i0 = 0; i0 < 2; ++i0)
            #pragma unroll
            for (int i1 = 0; i1 < 2; ++i1) {
                p01[i0 * 2 + i1] = cmul(i0 ? gb[0] : ga[0], i1 ? gb[1] : ga[1]);
                p23[i0 * 2 + i1] = cmul(i0 ? gb[2] : ga[2], i1 ? gb[3] : ga[3]);
            }
        #pragma unroll
        for (int hi = 0; hi < 4; ++hi)
            #pragma unroll
            for (int lo = 0; lo < 4; ++lo)
                amp[hi * 4 + lo] = cmul(p01[hi], p23[lo]);
    }

    // ---- entangling layers: 8 CNOTs (register swaps) + 4 Rot gates per layer ----
    const int cn_c[8] = {0, 1, 2, 3, 0, 1, 2, 3};
    const int cn_t[8] = {1, 2, 3, 0, 2, 3, 0, 1};
    for (int l = 0; l < L; ++l) {
        #pragma unroll
        for (int p = 0; p < 8; ++p) {
            const int cm = 8 >> cn_c[p];
            const int tm = 8 >> cn_t[p];
            #pragma unroll
            for (int i = 0; i < 16; ++i)
                if ((i & cm) && !(i & tm)) {
                    float2 tmp = amp[i]; amp[i] = amp[i | tm]; amp[i | tm] = tmp;
                }
        }
        #pragma unroll
        for (int w = 0; w < NQ; ++w) {
            const int m = 8 >> w;
            float4 Ua = rots4[(l * NQ + w) * 2 + 0];
            float4 Ub = rots4[(l * NQ + w) * 2 + 1];
            float2 u00 = make_float2(Ua.x, Ua.y);
            float2 u01 = make_float2(Ua.z, Ua.w);
            float2 u10 = make_float2(Ub.x, Ub.y);
            float2 u11 = make_float2(Ub.z, Ub.w);
            #pragma unroll
            for (int i = 0; i < 16; ++i)
                if (!(i & m)) {
                    float2 a0 = amp[i], a1 = amp[i | m];
                    amp[i]     = cfma(u01, a1, cmul(u00, a0));
                    amp[i | m] = cfma(u11, a1, cmul(u10, a0));
                }
        }
    }

    // ---- <Z_w> = sum_i (+/-)|amp_i|^2 ----
    float z0 = 0.f, z1 = 0.f, z2 = 0.f, z3 = 0.f;
    #pragma unroll
    for (int i = 0; i < 16; ++i) {
        float p = fmaf(amp[i].x, amp[i].x, amp[i].y * amp[i].y);
        z0 += (i & 8) ? -p : p;
        z1 += (i & 4) ? -p : p;
        z2 += (i & 2) ? -p : p;
        z3 += (i & 1) ? -p : p;
    }
    zs[tid] = make_float4(z0, z1, z2, z3);
    __syncthreads();

    // ---- out = z @ W2^T + b2, fully coalesced float4 stores ----
    #pragma unroll
    for (int k = 0; k < (ROWS * DOUT / 4) / THREADS; ++k) {   // 16 iters
        int q  = tid + k * THREADS;
        int r  = q >> 4;              // DOUT/4 = 16 float4 per row
        int j4 = q & 15;
        long row = rowBase + r;
        if (row < B) {
            float4 z = zs[r];
            const float4 w0 = *reinterpret_cast<const float4*>(&w2t[0][j4 * 4]);
            const float4 w1v = *reinterpret_cast<const float4*>(&w2t[1][j4 * 4]);
            const float4 w2v = *reinterpret_cast<const float4*>(&w2t[2][j4 * 4]);
            const float4 w3v = *reinterpret_cast<const float4*>(&w2t[3][j4 * 4]);
            float4 o = b2s4[j4];
            o.x = fmaf(z.x, w0.x, fmaf(z.y, w1v.x, fmaf(z.z, w2v.x, fmaf(z.w, w3v.x, o.x))));
            o.y = fmaf(z.x, w0.y, fmaf(z.y, w1v.y, fmaf(z.z, w2v.y, fmaf(z.w, w3v.y, o.y))));
            o.z = fmaf(z.x, w0.z, fmaf(z.y, w1v.z, fmaf(z.z, w2v.z, fmaf(z.w, w3v.z, o.z))));
            o.w = fmaf(z.x, w0.w, fmaf(z.y, w1v.w, fmaf(z.z, w2v.w, fmaf(z.w, w3v.w, o.w))));
            reinterpret_cast<float4*>(out + row * DOUT)[j4] = o;
        }
    }
}

extern "C" void kernel_launch(void* const* d_in, const int* in_sizes, int n_in,
                              void* d_out, int out_size) {
    const float* x       = (const float*)d_in[0];
    const float* W1      = (const float*)d_in[1];
    const float* b1      = (const float*)d_in[2];
    const float* weights = (const float*)d_in[3];
    const float* W2      = (const float*)d_in[4];
    const float* b2      = (const float*)d_in[5];
    float* out = (float*)d_out;

    int B = in_sizes[0] / DIN;
    int L = in_sizes[3] / (NQ * 3);
    if (L > MAX_L) L = MAX_L;

    rot_precompute_kernel<<<1, 64>>>(weights, L);

    int grid = (B + ROWS - 1) / ROWS;
    qproj_kernel<<<grid, THREADS>>>(x, W1, b1, W2, b2, out, B, L);
}

// round 2
// speedup vs baseline: 1.1923x; 1.1923x over previous
#include <cuda_runtime.h>
#include <math.h>

// x:(B,256) f32, W1:(4,256), b1:(4), weights:(L,4,3), W2:(64,4), b2:(64) -> out:(B,64)
#define MAX_L   8
#define DIN     256
#define DOUT    64
#define NQ      4
#define MAXB    (1 << 17)      // bench B = 131072
#define ROWS    256
#define THREADS 256

__device__ float  d_rot[MAX_L * NQ * 8];
__device__ float4 d_f[MAXB];   // 2 MB scratch: f = tanh(x@W1^T+b1)*pi per row

// ---------------------------------------------------------------------------
// Rot(phi,theta,omega) = Rz(omega) Ry(theta) Rz(phi), precomputed once.
// ---------------------------------------------------------------------------
__global__ void rot_precompute_kernel(const float* __restrict__ w, int L) {
    int idx = threadIdx.x;                 // l*4 + wire
    if (idx < L * NQ) {
        float phi = w[idx * 3 + 0];
        float th  = w[idx * 3 + 1];
        float om  = w[idx * 3 + 2];
        float s, c;   sincosf(0.5f * th, &s, &c);
        float sa, ca; sincosf(0.5f * (phi - om), &sa, &ca);
        float sb, cb; sincosf(0.5f * (phi + om), &sb, &cb);
        float* o = d_rot + idx * 8;
        o[0] =  cb * c;  o[1] = -sb * c;    // U00
        o[2] = -ca * s;  o[3] = -sa * s;    // U01
        o[4] =  ca * s;  o[5] = -sa * s;    // U10
        o[6] =  cb * c;  o[7] =  sb * c;    // U11
    }
}

// ---------------------------------------------------------------------------
// Kernel A: f-pass. Warp-cooperative, W1 in registers, MLP=8, persistent grid.
// Lane L covers cols [4L,4L+4) and [128+4L,128+4L+4).
// ---------------------------------------------------------------------------
__global__ void __launch_bounds__(THREADS)
f_kernel(const float* __restrict__ x, const float* __restrict__ W1,
         const float* __restrict__ b1, int B)
{
    const int lane = threadIdx.x & 31;
    const int gw   = blockIdx.x * (THREADS >> 5) + (threadIdx.x >> 5);
    const int nW   = gridDim.x * (THREADS >> 5);

    float4 wA[NQ], wB[NQ];
    #pragma unroll
    for (int q = 0; q < NQ; ++q) {
        wA[q] = *reinterpret_cast<const float4*>(W1 + q * DIN + 4 * lane);
        wB[q] = *reinterpret_cast<const float4*>(W1 + q * DIN + 128 + 4 * lane);
    }
    const float4 b1v  = *reinterpret_cast<const float4*>(b1);
    const float  PI_F = 3.14159265358979323846f;

    for (long base = (long)gw * 4; base < B; base += (long)nW * 4) {
        float4 xa[4], xb[4];
        #pragma unroll
        for (int r = 0; r < 4; ++r) {                    // 8 LDG.128 in flight
            long rr = base + r; if (rr >= B) rr = B - 1;
            const float* xp = x + rr * DIN + 4 * lane;
            xa[r] = *reinterpret_cast<const float4*>(xp);
            xb[r] = *reinterpret_cast<const float4*>(xp + 128);
        }
        float acc[4][NQ];
        #pragma unroll
        for (int r = 0; r < 4; ++r)
            #pragma unroll
            for (int q = 0; q < NQ; ++q) {
                float a;
                a = xa[r].x * wA[q].x;
                a = fmaf(xa[r].y, wA[q].y, a);
                a = fmaf(xa[r].z, wA[q].z, a);
                a = fmaf(xa[r].w, wA[q].w, a);
                a = fmaf(xb[r].x, wB[q].x, a);
                a = fmaf(xb[r].y, wB[q].y, a);
                a = fmaf(xb[r].z, wB[q].z, a);
                a = fmaf(xb[r].w, wB[q].w, a);
                acc[r][q] = a;
            }
        #pragma unroll
        for (int off = 16; off > 0; off >>= 1)
            #pragma unroll
            for (int r = 0; r < 4; ++r)
                #pragma unroll
                for (int q = 0; q < NQ; ++q)
                    acc[r][q] += __shfl_xor_sync(0xffffffffu, acc[r][q], off);

        if (lane < 4 && base + lane < B) {
            float4 o;
            o.x = tanhf(acc[lane][0] + b1v.x) * PI_F;
            o.y = tanhf(acc[lane][1] + b1v.y) * PI_F;
            o.z = tanhf(acc[lane][2] + b1v.z) * PI_F;
            o.w = tanhf(acc[lane][3] + b1v.w) * PI_F;
            d_f[base + lane] = o;
        }
    }
}

__device__ __forceinline__ float2 cmul(float2 a, float2 b) {
    return make_float2(fmaf(a.x, b.x, -a.y * b.y), fmaf(a.x, b.y, a.y * b.x));
}
__device__ __forceinline__ float2 cfma(float2 u, float2 a, float2 acc) {
    acc.x = fmaf(u.x, a.x, fmaf(-u.y, a.y, acc.x));
    acc.y = fmaf(u.x, a.y, fmaf( u.y, a.x, acc.y));
    return acc;
}

// ---------------------------------------------------------------------------
// Kernel B: circuit + projection. One thread = one row; f read coalesced.
// ---------------------------------------------------------------------------
__global__ void __launch_bounds__(THREADS)
circuit_kernel(const float* __restrict__ W2, const float* __restrict__ b2,
               float* __restrict__ out, int B, int L)
{
    __shared__ float  w2t[NQ][DOUT];
    __shared__ float4 b2s4[DOUT / 4];
    __shared__ float4 rots4[MAX_L * NQ * 2];
    __shared__ float4 zs[ROWS];

    const int  tid     = threadIdx.x;
    const long rowBase = (long)blockIdx.x * ROWS;

    if (tid < DOUT) {
        #pragma unroll
        for (int i = 0; i < NQ; ++i) w2t[i][tid] = W2[tid * NQ + i];
    }
    if (tid < DOUT / 4) b2s4[tid] = reinterpret_cast<const float4*>(b2)[tid];
    for (int i = tid; i < L * NQ * 2; i += THREADS)
        rots4[i] = reinterpret_cast<const float4*>(d_rot)[i];

    long myRow = rowBase + tid; if (myRow >= B) myRow = B - 1;
    const float4 fvv = d_f[myRow];
    float fv[NQ] = {fvv.x, fvv.y, fvv.z, fvv.w};

    // H, RY(atan f), RZ(atan f^2) product state per qubit (atan eliminated):
    // sin(atan t) = t/sqrt(1+t^2); cos(atan t^2) = 1/sqrt(1+t^4); half-angle sqrts.
    float2 ga[NQ], gb[NQ];
    #pragma unroll
    for (int i = 0; i < NQ; ++i) {
        float t  = fv[i];
        float t2 = t * t;
        float st = t * rsqrtf(1.f + t2);
        float u  = sqrtf(fmaxf(0.5f * (1.f - st), 0.f));
        float v  = sqrtf(fmaxf(0.5f * (1.f + st), 0.f));
        float t4 = t2 * t2;
        float r2 = rsqrtf(1.f + t4);
        float cp = sqrtf(fmaxf(0.5f * (1.f + r2), 0.f));
        float sp = sqrtf(fmaxf(0.5f * (1.f - r2), 0.f));
        ga[i] = make_float2(u * cp, -u * sp);
        gb[i] = make_float2(v * cp,  v * sp);
    }

    float2 amp[16];
    {
        float2 p01[4], p23[4];
        #pragma unroll
        for (int i0 = 0; i0 < 2; ++i0)
            #pragma unroll
            for (int i1 = 0; i1 < 2; ++i1) {
                p01[i0 * 2 + i1] = cmul(i0 ? gb[0] : ga[0], i1 ? gb[1] : ga[1]);
                p23[i0 * 2 + i1] = cmul(i0 ? gb[2] : ga[2], i1 ? gb[3] : ga[3]);
            }
        #pragma unroll
        for (int hi = 0; hi < 4; ++hi)
            #pragma unroll
            for (int lo = 0; lo < 4; ++lo)
                amp[hi * 4 + lo] = cmul(p01[hi], p23[lo]);
    }

    const int cn_c[8] = {0, 1, 2, 3, 0, 1, 2, 3};
    const int cn_t[8] = {1, 2, 3, 0, 2, 3, 0, 1};
    for (int l = 0; l < L; ++l) {
        #pragma unroll
        for (int p = 0; p < 8; ++p) {
            const int cm = 8 >> cn_c[p];
            const int tm = 8 >> cn_t[p];
            #pragma unroll
            for (int i = 0; i < 16; ++i)
                if ((i & cm) && !(i & tm)) {
                    float2 tmp = amp[i]; amp[i] = amp[i | tm]; amp[i | tm] = tmp;
                }
        }
        #pragma unroll
        for (int w = 0; w < NQ; ++w) {
            const int m = 8 >> w;
            float4 Ua = rots4[(l * NQ + w) * 2 + 0];
            float4 Ub = rots4[(l * NQ + w) * 2 + 1];
            float2 u00 = make_float2(Ua.x, Ua.y);
            float2 u01 = make_float2(Ua.z, Ua.w);
            float2 u10 = make_float2(Ub.x, Ub.y);
            float2 u11 = make_float2(Ub.z, Ub.w);
            #pragma unroll
            for (int i = 0; i < 16; ++i)
                if (!(i & m)) {
                    float2 a0 = amp[i], a1 = amp[i | m];
                    amp[i]     = cfma(u01, a1, cmul(u00, a0));
                    amp[i | m] = cfma(u11, a1, cmul(u10, a0));
                }
        }
    }

    float z0 = 0.f, z1 = 0.f, z2 = 0.f, z3 = 0.f;
    #pragma unroll
    for (int i = 0; i < 16; ++i) {
        float p = fmaf(amp[i].x, amp[i].x, amp[i].y * amp[i].y);
        z0 += (i & 8) ? -p : p;
        z1 += (i & 4) ? -p : p;
        z2 += (i & 2) ? -p : p;
        z3 += (i & 1) ? -p : p;
    }
    zs[tid] = make_float4(z0, z1, z2, z3);
    __syncthreads();

    #pragma unroll
    for (int k = 0; k < (ROWS * DOUT / 4) / THREADS; ++k) {
        int q  = tid + k * THREADS;
        int r  = q >> 4;
        int j4 = q & 15;
        long row = rowBase + r;
        if (row < B) {
            float4 z = zs[r];
            const float4 w0  = *reinterpret_cast<const float4*>(&w2t[0][j4 * 4]);
            const float4 w1v = *reinterpret_cast<const float4*>(&w2t[1][j4 * 4]);
            const float4 w2v = *reinterpret_cast<const float4*>(&w2t[2][j4 * 4]);
            const float4 w3v = *reinterpret_cast<const float4*>(&w2t[3][j4 * 4]);
            float4 o = b2s4[j4];
            o.x = fmaf(z.x, w0.x, fmaf(z.y, w1v.x, fmaf(z.z, w2v.x, fmaf(z.w, w3v.x, o.x))));
            o.y = fmaf(z.x, w0.y, fmaf(z.y, w1v.y, fmaf(z.z, w2v.y, fmaf(z.w, w3v.y, o.y))));
            o.z = fmaf(z.x, w0.z, fmaf(z.y, w1v.z, fmaf(z.z, w2v.z, fmaf(z.w, w3v.z, o.z))));
            o.w = fmaf(z.x, w0.w, fmaf(z.y, w1v.w, fmaf(z.z, w2v.w, fmaf(z.w, w3v.w, o.w))));
            reinterpret_cast<float4*>(out + row * DOUT)[j4] = o;
        }
    }
}

extern "C" void kernel_launch(void* const* d_in, const int* in_sizes, int n_in,
                              void* d_out, int out_size) {
    const float* x       = (const float*)d_in[0];
    const float* W1      = (const float*)d_in[1];
    const float* b1      = (const float*)d_in[2];
    const float* weights = (const float*)d_in[3];
    const float* W2      = (const float*)d_in[4];
    const float* b2      = (const float*)d_in[5];
    float* out = (float*)d_out;

    int B = in_sizes[0] / DIN;
    if (B > MAXB) B = MAXB;
    int L = in_sizes[3] / (NQ * 3);
    if (L > MAX_L) L = MAX_L;

    rot_precompute_kernel<<<1, 64>>>(weights, L);

    int fgrid = 148 * 8;                       // persistent-ish grid for f-pass
    int maxWarpQuads = (B + 3) / 4;
    int maxBlocks = (maxWarpQuads + (THREADS / 32) - 1) / (THREADS / 32);
    if (fgrid > maxBlocks) fgrid = maxBlocks;
    f_kernel<<<fgrid, THREADS>>>(x, W1, b1, B);

    int grid = (B + ROWS - 1) / ROWS;
    circuit_kernel<<<grid, THREADS>>>(W2, b2, out, B, L);
}

// round 4
// speedup vs baseline: 1.2942x; 1.0855x over previous
#include <cuda_runtime.h>
#include <math.h>

// x:(B,256) f32, W1:(4,256), b1:(4), weights:(L,4,3), W2:(64,4), b2:(64) -> out:(B,64)
#define MAX_L   8
#define DIN     256
#define DOUT    64
#define NQ      4
#define ROWS    256
#define THREADS 256

__device__ __forceinline__ float2 cmul(float2 a, float2 b) {
    return make_float2(fmaf(a.x, b.x, -a.y * b.y), fmaf(a.x, b.y, a.y * b.x));
}
__device__ __forceinline__ float2 cfma(float2 u, float2 a, float2 acc) {
    acc.x = fmaf(u.x, a.x, fmaf(-u.y, a.y, acc.x));
    acc.y = fmaf(u.x, a.y, fmaf( u.y, a.x, acc.y));
    return acc;
}
// tanh via MUFU exp: tanh(x) = 1 - 2/(exp(2x)+1). |err| ~ 1e-7 rel.
__device__ __forceinline__ float fast_tanh(float v) {
    float e = __expf(2.f * v);
    return 1.f - 2.f * __frcp_rn(e + 1.f);
}

// ---------------------------------------------------------------------------
// Single fused kernel. Block = 256 threads = 256 rows.
// Phase 1 (warp-coop GEMV): warp owns 32 rows; 8 sub-iters x 4 rows;
//   lane covers cols [4L,4L+4) and [128+4L,..+4). Full xor-butterfly leaves
//   all 4 row-sums in every lane; lane j keeps sub-iter (j>>2)'s row.
// Phase 2: every lane runs the 4-qubit circuit for its own row.
// Phase 3: z staged in smem, fully coalesced float4 projection stores.
// ---------------------------------------------------------------------------
__global__ void __launch_bounds__(THREADS, 2)
qproj_fused(const float* __restrict__ x,  const float* __restrict__ W1,
            const float* __restrict__ b1, const float* __restrict__ weights,
            const float* __restrict__ W2, const float* __restrict__ b2,
            float* __restrict__ out, int B, int L)
{
    __shared__ float  w2t[NQ][DOUT];
    __shared__ float4 b2s4[DOUT / 4];
    __shared__ float4 rots4[MAX_L * NQ * 2];
    __shared__ float4 zs[ROWS];

    const int  tid     = threadIdx.x;
    const int  lane    = tid & 31;
    const int  wid     = tid >> 5;
    const long rowBase = (long)blockIdx.x * ROWS;
    const bool fullBlk = (rowBase + ROWS) <= (long)B;

    // ---- stage small weights + compute Rot matrices in-block ----
    if (tid < DOUT) {
        #pragma unroll
        for (int i = 0; i < NQ; ++i) w2t[i][tid] = W2[tid * NQ + i];
    }
    if (tid < DOUT / 4) b2s4[tid] = reinterpret_cast<const float4*>(b2)[tid];
    if (tid >= 64 && tid < 64 + L * NQ) {
        int idx = tid - 64;                 // l*4 + wire
        float phi = weights[idx * 3 + 0];
        float th  = weights[idx * 3 + 1];
        float om  = weights[idx * 3 + 2];
        float s, c;   sincosf(0.5f * th, &s, &c);
        float sa, ca; sincosf(0.5f * (phi - om), &sa, &ca);   // (phi-omega)/2
        float sb, cb; sincosf(0.5f * (phi + om), &sb, &cb);   // (phi+omega)/2
        rots4[idx * 2 + 0] = make_float4( cb * c, -sb * c,    // U00
                                         -ca * s, -sa * s);   // U01
        rots4[idx * 2 + 1] = make_float4( ca * s, -sa * s,    // U10
                                          cb * c,  sb * c);   // U11
    }

    // ---- phase 1: f = tanh(x @ W1^T + b1) * pi (warp-cooperative) ----
    float4 wA[NQ], wB[NQ];
    #pragma unroll
    for (int q = 0; q < NQ; ++q) {
        wA[q] = *reinterpret_cast<const float4*>(W1 + q * DIN + 4 * lane);
        wB[q] = *reinterpret_cast<const float4*>(W1 + q * DIN + 128 + 4 * lane);
    }
    const float4 b1v = *reinterpret_cast<const float4*>(b1);

    const long warpRow = rowBase + wid * 32;
    float m0 = 0.f, m1 = 0.f, m2 = 0.f, m3 = 0.f;   // my row's 4 dot products

    #pragma unroll
    for (int s = 0; s < 8; ++s) {
        float4 xa[4], xb[4];
        if (fullBlk) {
            #pragma unroll
            for (int r = 0; r < 4; ++r) {            // 8 LDG.128 in flight
                const float* xp = x + (warpRow + s * 4 + r) * DIN + 4 * lane;
                xa[r] = *reinterpret_cast<const float4*>(xp);
                xb[r] = *reinterpret_cast<const float4*>(xp + 128);
            }
        } else {
            #pragma unroll
            for (int r = 0; r < 4; ++r) {
                long rr = warpRow + s * 4 + r;
                if (rr >= B) rr = (long)B - 1;
                const float* xp = x + rr * DIN + 4 * lane;
                xa[r] = *reinterpret_cast<const float4*>(xp);
                xb[r] = *reinterpret_cast<const float4*>(xp + 128);
            }
        }
        float acc[4][NQ];
        #pragma unroll
        for (int r = 0; r < 4; ++r)
            #pragma unroll
            for (int q = 0; q < NQ; ++q) {
                float a;
                a = xa[r].x * wA[q].x;
                a = fmaf(xa[r].y, wA[q].y, a);
                a = fmaf(xa[r].z, wA[q].z, a);
                a = fmaf(xa[r].w, wA[q].w, a);
                a = fmaf(xb[r].x, wB[q].x, a);
                a = fmaf(xb[r].y, wB[q].y, a);
                a = fmaf(xb[r].z, wB[q].z, a);
                a = fmaf(xb[r].w, wB[q].w, a);
                acc[r][q] = a;
            }
        #pragma unroll
        for (int off = 16; off > 0; off >>= 1)
            #pragma unroll
            for (int r = 0; r < 4; ++r)
                #pragma unroll
                for (int q = 0; q < NQ; ++q)
                    acc[r][q] += __shfl_xor_sync(0xffffffffu, acc[r][q], off);
        // all lanes now hold the full sums for rows s*4..s*4+3
        if ((lane >> 2) == s) {
            int r = lane & 3;
            m0 = acc[r][0]; m1 = acc[r][1]; m2 = acc[r][2]; m3 = acc[r][3];
        }
    }

    const float PI_F = 3.14159265358979323846f;
    float fv[NQ];
    fv[0] = fast_tanh(m0 + b1v.x) * PI_F;
    fv[1] = fast_tanh(m1 + b1v.y) * PI_F;
    fv[2] = fast_tanh(m2 + b1v.z) * PI_F;
    fv[3] = fast_tanh(m3 + b1v.w) * PI_F;

    // ---- phase 2: circuit (per-lane row; atan eliminated via identities) ----
    // sin(atan t) = t*rsqrt(1+t^2); cos(atan t^2) = rsqrt(1+t^4); half-angles.
    float2 ga[NQ], gb[NQ];
    #pragma unroll
    for (int i = 0; i < NQ; ++i) {
        float t  = fv[i];
        float t2 = t * t;
        float st = t * rsqrtf(1.f + t2);
        float u  = sqrtf(fmaxf(0.5f * (1.f - st), 0.f));
        float v  = sqrtf(fmaxf(0.5f * (1.f + st), 0.f));
        float t4 = t2 * t2;
        float r2 = rsqrtf(1.f + t4);
        float cp = sqrtf(fmaxf(0.5f * (1.f + r2), 0.f));
        float sp = sqrtf(fmaxf(0.5f * (1.f - r2), 0.f));
        ga[i] = make_float2(u * cp, -u * sp);
        gb[i] = make_float2(v * cp,  v * sp);
    }

    float2 amp[16];
    {
        float2 p01[4], p23[4];
        #pragma unroll
        for (int i0 = 0; i0 < 2; ++i0)
            #pragma unroll
            for (int i1 = 0; i1 < 2; ++i1) {
                p01[i0 * 2 + i1] = cmul(i0 ? gb[0] : ga[0], i1 ? gb[1] : ga[1]);
                p23[i0 * 2 + i1] = cmul(i0 ? gb[2] : ga[2], i1 ? gb[3] : ga[3]);
            }
        #pragma unroll
        for (int hi = 0; hi < 4; ++hi)
            #pragma unroll
            for (int lo = 0; lo < 4; ++lo)
                amp[hi * 4 + lo] = cmul(p01[hi], p23[lo]);
    }

    __syncthreads();   // rots4/w2t/b2s4 ready (also orders zs writes below)

    const int cn_c[8] = {0, 1, 2, 3, 0, 1, 2, 3};
    const int cn_t[8] = {1, 2, 3, 0, 2, 3, 0, 1};
    for (int l = 0; l < L; ++l) {
        #pragma unroll
        for (int p = 0; p < 8; ++p) {
            const int cm = 8 >> cn_c[p];
            const int tm = 8 >> cn_t[p];
            #pragma unroll
            for (int i = 0; i < 16; ++i)
                if ((i & cm) && !(i & tm)) {
                    float2 tmp = amp[i]; amp[i] = amp[i | tm]; amp[i | tm] = tmp;
                }
        }
        #pragma unroll
        for (int w = 0; w < NQ; ++w) {
            const int m = 8 >> w;
            float4 Ua = rots4[(l * NQ + w) * 2 + 0];
            float4 Ub = rots4[(l * NQ + w) * 2 + 1];
            float2 u00 = make_float2(Ua.x, Ua.y);
            float2 u01 = make_float2(Ua.z, Ua.w);
            float2 u10 = make_float2(Ub.x, Ub.y);
            float2 u11 = make_float2(Ub.z, Ub.w);
            #pragma unroll
            for (int i = 0; i < 16; ++i)
                if (!(i & m)) {
                    float2 a0 = amp[i], a1 = amp[i | m];
                    amp[i]     = cfma(u01, a1, cmul(u00, a0));
                    amp[i | m] = cfma(u11, a1, cmul(u10, a0));
                }
        }
    }

    float z0 = 0.f, z1 = 0.f, z2 = 0.f, z3 = 0.f;
    #pragma unroll
    for (int i = 0; i < 16; ++i) {
        float p = fmaf(amp[i].x, amp[i].x, amp[i].y * amp[i].y);
        z0 += (i & 8) ? -p : p;
        z1 += (i & 4) ? -p : p;
        z2 += (i & 2) ? -p : p;
        z3 += (i & 1) ? -p : p;
    }
    zs[wid * 32 + lane] = make_float4(z0, z1, z2, z3);
    __syncthreads();

    // ---- phase 3: out = z @ W2^T + b2, coalesced float4 stores ----
    #pragma unroll
    for (int k = 0; k < (ROWS * DOUT / 4) / THREADS; ++k) {   // 16 iters
        int q  = tid + k * THREADS;
        int r  = q >> 4;
        int j4 = q & 15;
        long row = rowBase + r;
        if (row < B) {
            float4 z = zs[r];
            const float4 w0  = *reinterpret_cast<const float4*>(&w2t[0][j4 * 4]);
            const float4 w1v = *reinterpret_cast<const float4*>(&w2t[1][j4 * 4]);
            const float4 w2v = *reinterpret_cast<const float4*>(&w2t[2][j4 * 4]);
            const float4 w3v = *reinterpret_cast<const float4*>(&w2t[3][j4 * 4]);
            float4 o = b2s4[j4];
            o.x = fmaf(z.x, w0.x, fmaf(z.y, w1v.x, fmaf(z.z, w2v.x, fmaf(z.w, w3v.x, o.x))));
            o.y = fmaf(z.x, w0.y, fmaf(z.y, w1v.y, fmaf(z.z, w2v.y, fmaf(z.w, w3v.y, o.y))));
            o.z = fmaf(z.x, w0.z, fmaf(z.y, w1v.z, fmaf(z.z, w2v.z, fmaf(z.w, w3v.z, o.z))));
            o.w = fmaf(z.x, w0.w, fmaf(z.y, w1v.w, fmaf(z.z, w2v.w, fmaf(z.w, w3v.w, o.w))));
            reinterpret_cast<float4*>(out + row * DOUT)[j4] = o;
        }
    }
}

extern "C" void kernel_launch(void* const* d_in, const int* in_sizes, int n_in,
                              void* d_out, int out_size) {
    const float* x       = (const float*)d_in[0];
    const float* W1      = (const float*)d_in[1];
    const float* b1      = (const float*)d_in[2];
    const float* weights = (const float*)d_in[3];
    const float* W2      = (const float*)d_in[4];
    const float* b2      = (const float*)d_in[5];
    float* out = (float*)d_out;

    int B = in_sizes[0] / DIN;
    int L = in_sizes[3] / (NQ * 3);
    if (L > MAX_L) L = MAX_L;

    int grid = (B + ROWS - 1) / ROWS;
    qproj_fused<<<grid, THREADS>>>(x, W1, b1, weights, W2, b2, out, B, L);
}

// round 5
// speedup vs baseline: 1.4101x; 1.0896x over previous
#include <cuda_runtime.h>
#include <math.h>

// x:(B,256) f32, W1:(4,256), b1:(4), weights:(L,4,3), W2:(64,4), b2:(64) -> out:(B,64)
#define MAX_L   8
#define DIN     256
#define DOUT    64
#define NQ      4
#define ROWS    256
#define THREADS 256

__device__ __forceinline__ float2 cmul(float2 a, float2 b) {
    return make_float2(fmaf(a.x, b.x, -a.y * b.y), fmaf(a.x, b.y, a.y * b.x));
}
__device__ __forceinline__ float2 cfma(float2 u, float2 a, float2 acc) {
    acc.x = fmaf(u.x, a.x, fmaf(-u.y, a.y, acc.x));
    acc.y = fmaf(u.x, a.y, fmaf( u.y, a.x, acc.y));
    return acc;
}
// tanh via MUFU exp: tanh(x) = 1 - 2/(exp(2x)+1). |err| ~ 1e-7 rel.
__device__ __forceinline__ float fast_tanh(float v) {
    float e = __expf(2.f * v);
    return 1.f - 2.f * __frcp_rn(e + 1.f);
}

// ---------------------------------------------------------------------------
// Single fused kernel. Block = 256 threads = 256 rows.
// Phase 1 (warp-coop GEMV): warp owns 32 rows; 8 sub-iters x 4 rows.
//   Value-halving butterfly: off=16 keeps 2 rows (8 SHFL), off=8 keeps 1 row
//   (4 SHFL), full butterfly on 4 q-values (12 SHFL), 4-SHFL redistribution.
// Phase 2: every lane runs the 4-qubit circuit for its own row.
// Phase 3: z staged in smem, fully coalesced float4 projection stores.
// ---------------------------------------------------------------------------
__global__ void __launch_bounds__(THREADS, 2)
qproj_fused(const float* __restrict__ x,  const float* __restrict__ W1,
            const float* __restrict__ b1, const float* __restrict__ weights,
            const float* __restrict__ W2, const float* __restrict__ b2,
            float* __restrict__ out, int B, int L)
{
    __shared__ float  w2t[NQ][DOUT];
    __shared__ float4 b2s4[DOUT / 4];
    __shared__ float4 rots4[MAX_L * NQ * 2];
    __shared__ float4 zs[ROWS];

    const int  tid     = threadIdx.x;
    const int  lane    = tid & 31;
    const int  wid     = tid >> 5;
    const long rowBase = (long)blockIdx.x * ROWS;
    const bool fullBlk = (rowBase + ROWS) <= (long)B;

    // ---- stage small weights + compute Rot matrices in-block ----
    if (tid < DOUT) {
        #pragma unroll
        for (int i = 0; i < NQ; ++i) w2t[i][tid] = W2[tid * NQ + i];
    }
    if (tid < DOUT / 4) b2s4[tid] = reinterpret_cast<const float4*>(b2)[tid];
    if (tid >= 64 && tid < 64 + L * NQ) {
        int idx = tid - 64;                 // l*4 + wire
        float phi = weights[idx * 3 + 0];
        float th  = weights[idx * 3 + 1];
        float om  = weights[idx * 3 + 2];
        float s, c;   sincosf(0.5f * th, &s, &c);
        float sa, ca; sincosf(0.5f * (phi - om), &sa, &ca);   // (phi-omega)/2
        float sb, cb; sincosf(0.5f * (phi + om), &sb, &cb);   // (phi+omega)/2
        rots4[idx * 2 + 0] = make_float4( cb * c, -sb * c,    // U00
                                         -ca * s, -sa * s);   // U01
        rots4[idx * 2 + 1] = make_float4( ca * s, -sa * s,    // U10
                                          cb * c,  sb * c);   // U11
    }

    // ---- phase 1: f = tanh(x @ W1^T + b1) * pi (warp-cooperative) ----
    float4 wA[NQ], wB[NQ];
    #pragma unroll
    for (int q = 0; q < NQ; ++q) {
        wA[q] = *reinterpret_cast<const float4*>(W1 + q * DIN + 4 * lane);
        wB[q] = *reinterpret_cast<const float4*>(W1 + q * DIN + 128 + 4 * lane);
    }
    const float4 b1v = *reinterpret_cast<const float4*>(b1);

    const long warpRow = rowBase + wid * 32;
    const bool hiR1 = (lane & 16) != 0;     // keep rows {2,3} at off=16
    const bool hiR0 = (lane & 8)  != 0;     // keep odd row of pair at off=8
    const int  redisSrc = 8 * (lane & 3);   // source lane for my row's sums

    float m0 = 0.f, m1 = 0.f, m2 = 0.f, m3 = 0.f;   // my row's 4 dot products

    #pragma unroll
    for (int s = 0; s < 8; ++s) {
        float4 xa[4], xb[4];
        if (fullBlk) {
            #pragma unroll
            for (int r = 0; r < 4; ++r) {            // 8 LDG.128 in flight
                const float* xp = x + (warpRow + s * 4 + r) * DIN + 4 * lane;
                xa[r] = *reinterpret_cast<const float4*>(xp);
                xb[r] = *reinterpret_cast<const float4*>(xp + 128);
            }
        } else {
            #pragma unroll
            for (int r = 0; r < 4; ++r) {
                long rr = warpRow + s * 4 + r;
                if (rr >= B) rr = (long)B - 1;
                const float* xp = x + rr * DIN + 4 * lane;
                xa[r] = *reinterpret_cast<const float4*>(xp);
                xb[r] = *reinterpret_cast<const float4*>(xp + 128);
            }
        }
        float acc[4][NQ];
        #pragma unroll
        for (int r = 0; r < 4; ++r)
            #pragma unroll
            for (int q = 0; q < NQ; ++q) {
                float a;
                a = xa[r].x * wA[q].x;
                a = fmaf(xa[r].y, wA[q].y, a);
                a = fmaf(xa[r].z, wA[q].z, a);
                a = fmaf(xa[r].w, wA[q].w, a);
                a = fmaf(xb[r].x, wB[q].x, a);
                a = fmaf(xb[r].y, wB[q].y, a);
                a = fmaf(xb[r].z, wB[q].z, a);
                a = fmaf(xb[r].w, wB[q].w, a);
                acc[r][q] = a;
            }

        // ---- value-halving butterfly ----
        // off=16: keep rows {2*hiR1, 2*hiR1+1}, give the other two. Symmetric
        // indexing: my give[rl][q] is the value my partner keeps, so one SHFL
        // per kept value serves both lanes.
        float t8[2][NQ];
        #pragma unroll
        for (int rl = 0; rl < 2; ++rl)
            #pragma unroll
            for (int q = 0; q < NQ; ++q) {
                float kp = hiR1 ? acc[rl + 2][q] : acc[rl][q];
                float gv = hiR1 ? acc[rl][q]     : acc[rl + 2][q];
                t8[rl][q] = kp + __shfl_xor_sync(0xffffffffu, gv, 16);
            }
        // off=8: keep row (2*hiR1 + hiR0)
        float t4[NQ];
        #pragma unroll
        for (int q = 0; q < NQ; ++q) {
            float kp = hiR0 ? t8[1][q] : t8[0][q];
            float gv = hiR0 ? t8[0][q] : t8[1][q];
            t4[q] = kp + __shfl_xor_sync(0xffffffffu, gv, 8);
        }
        // off=4,2,1: full butterfly on the 4 surviving q-values.
        // Afterwards every lane holds the complete sums for row r* = lane>>3.
        #pragma unroll
        for (int off = 4; off >= 1; off >>= 1)
            #pragma unroll
            for (int q = 0; q < NQ; ++q)
                t4[q] += __shfl_xor_sync(0xffffffffu, t4[q], off);

        // redistribute: lane j wants row (j&3), held by lanes 8*(j&3)..+7
        float r0 = __shfl_sync(0xffffffffu, t4[0], redisSrc);
        float r1 = __shfl_sync(0xffffffffu, t4[1], redisSrc);
        float r2 = __shfl_sync(0xffffffffu, t4[2], redisSrc);
        float r3 = __shfl_sync(0xffffffffu, t4[3], redisSrc);
        if ((lane >> 2) == s) { m0 = r0; m1 = r1; m2 = r2; m3 = r3; }
    }

    const float PI_F = 3.14159265358979323846f;
    float fv[NQ];
    fv[0] = fast_tanh(m0 + b1v.x) * PI_F;
    fv[1] = fast_tanh(m1 + b1v.y) * PI_F;
    fv[2] = fast_tanh(m2 + b1v.z) * PI_F;
    fv[3] = fast_tanh(m3 + b1v.w) * PI_F;

    // ---- phase 2: circuit (per-lane row; atan eliminated via identities) ----
    // sin(atan t) = t*rsqrt(1+t^2); cos(atan t^2) = rsqrt(1+t^4); half-angles.
    float2 ga[NQ], gb[NQ];
    #pragma unroll
    for (int i = 0; i < NQ; ++i) {
        float t  = fv[i];
        float t2 = t * t;
        float st = t * rsqrtf(1.f + t2);
        float u  = sqrtf(fmaxf(0.5f * (1.f - st), 0.f));
        float v  = sqrtf(fmaxf(0.5f * (1.f + st), 0.f));
        float t4 = t2 * t2;
        float r2 = rsqrtf(1.f + t4);
        float cp = sqrtf(fmaxf(0.5f * (1.f + r2), 0.f));
        float sp = sqrtf(fmaxf(0.5f * (1.f - r2), 0.f));
        ga[i] = make_float2(u * cp, -u * sp);
        gb[i] = make_float2(v * cp,  v * sp);
    }

    float2 amp[16];
    {
        float2 p01[4], p23[4];
        #pragma unroll
        for (int i0 = 0; i0 < 2; ++i0)
            #pragma unroll
            for (int i1 = 0; i1 < 2; ++i1) {
                p01[i0 * 2 + i1] = cmul(i0 ? gb[0] : ga[0], i1 ? gb[1] : ga[1]);
                p23[i0 * 2 + i1] = cmul(i0 ? gb[2] : ga[2], i1 ? gb[3] : ga[3]);
            }
        #pragma unroll
        for (int hi = 0; hi < 4; ++hi)
            #pragma unroll
            for (int lo = 0; lo < 4; ++lo)
                amp[hi * 4 + lo] = cmul(p01[hi], p23[lo]);
    }

    __syncthreads();   // rots4/w2t/b2s4 ready (also orders zs writes below)

    const int cn_c[8] = {0, 1, 2, 3, 0, 1, 2, 3};
    const int cn_t[8] = {1, 2, 3, 0, 2, 3, 0, 1};
    for (int l = 0; l < L; ++l) {
        #pragma unroll
        for (int p = 0; p < 8; ++p) {
            const int cm = 8 >> cn_c[p];
            const int tm = 8 >> cn_t[p];
            #pragma unroll
            for (int i = 0; i < 16; ++i)
                if ((i & cm) && !(i & tm)) {
                    float2 tmp = amp[i]; amp[i] = amp[i | tm]; amp[i | tm] = tmp;
                }
        }
        #pragma unroll
        for (int w = 0; w < NQ; ++w) {
            const int m = 8 >> w;
            float4 Ua = rots4[(l * NQ + w) * 2 + 0];
            float4 Ub = rots4[(l * NQ + w) * 2 + 1];
            float2 u00 = make_float2(Ua.x, Ua.y);
            float2 u01 = make_float2(Ua.z, Ua.w);
            float2 u10 = make_float2(Ub.x, Ub.y);
            float2 u11 = make_float2(Ub.z, Ub.w);
            #pragma unroll
            for (int i = 0; i < 16; ++i)
                if (!(i & m)) {
                    float2 a0 = amp[i], a1 = amp[i | m];
                    amp[i]     = cfma(u01, a1, cmul(u00, a0));
                    amp[i | m] = cfma(u11, a1, cmul(u10, a0));
                }
        }
    }

    float z0 = 0.f, z1 = 0.f, z2 = 0.f, z3 = 0.f;
    #pragma unroll
    for (int i = 0; i < 16; ++i) {
        float p = fmaf(amp[i].x, amp[i].x, amp[i].y * amp[i].y);
        z0 += (i & 8) ? -p : p;
        z1 += (i & 4) ? -p : p;
        z2 += (i & 2) ? -p : p;
        z3 += (i & 1) ? -p : p;
    }
    zs[wid * 32 + lane] = make_float4(z0, z1, z2, z3);
    __syncthreads();

    // ---- phase 3: out = z @ W2^T + b2, coalesced float4 stores ----
    #pragma unroll
    for (int k = 0; k < (ROWS * DOUT / 4) / THREADS; ++k) {   // 16 iters
        int q  = tid + k * THREADS;
        int r  = q >> 4;
        int j4 = q & 15;
        long row = rowBase + r;
        if (row < B) {
            float4 z = zs[r];
            const float4 w0  = *reinterpret_cast<const float4*>(&w2t[0][j4 * 4]);
            const float4 w1v = *reinterpret_cast<const float4*>(&w2t[1][j4 * 4]);
            const float4 w2v = *reinterpret_cast<const float4*>(&w2t[2][j4 * 4]);
            const float4 w3v = *reinterpret_cast<const float4*>(&w2t[3][j4 * 4]);
            float4 o = b2s4[j4];
            o.x = fmaf(z.x, w0.x, fmaf(z.y, w1v.x, fmaf(z.z, w2v.x, fmaf(z.w, w3v.x, o.x))));
            o.y = fmaf(z.x, w0.y, fmaf(z.y, w1v.y, fmaf(z.z, w2v.y, fmaf(z.w, w3v.y, o.y))));
            o.z = fmaf(z.x, w0.z, fmaf(z.y, w1v.z, fmaf(z.z, w2v.z, fmaf(z.w, w3v.z, o.z))));
            o.w = fmaf(z.x, w0.w, fmaf(z.y, w1v.w, fmaf(z.z, w2v.w, fmaf(z.w, w3v.w, o.w))));
            reinterpret_cast<float4*>(out + row * DOUT)[j4] = o;
        }
    }
}

extern "C" void kernel_launch(void* const* d_in, const int* in_sizes, int n_in,
                              void* d_out, int out_size) {
    const float* x       = (const float*)d_in[0];
    const float* W1      = (const float*)d_in[1];
    const float* b1      = (const float*)d_in[2];
    const float* weights = (const float*)d_in[3];
    const float* W2      = (const float*)d_in[4];
    const float* b2      = (const float*)d_in[5];
    float* out = (float*)d_out;

    int B = in_sizes[0] / DIN;
    int L = in_sizes[3] / (NQ * 3);
    if (L > MAX_L) L = MAX_L;

    int grid = (B + ROWS - 1) / ROWS;
    qproj_fused<<<grid, THREADS>>>(x, W1, b1, weights, W2, b2, out, B, L);
}